// round 5
// baseline (speedup 1.0000x reference)
#include <cuda_runtime.h>
#include <cstdint>

#define DD 128
#define N_MAX 50000
#define CAP_E (1 << 20)

// CSR machinery
static __device__ int g_cnt[N_MAX];
static __device__ int g_off[N_MAX + 1];
static __device__ int g_cur[N_MAX];
static __device__ int g_eidx[CAP_E];   // src index per dst-sorted edge
// fallback-path scratch (only used when E > CAP_E)
static __device__ float4 g_h4[(size_t)N_MAX * (DD / 4)];

// ---------------------------------------------------------------------------
// Index dtype detection: reference declares int64 indices but JAX with x64
// disabled emits int32. First 4 elements viewed as int64 land in [0,N) only
// if the data really is int64.
// ---------------------------------------------------------------------------
__device__ __forceinline__ bool detect_i64(const void* p, int N) {
    const long long* q = (const long long*)p;
    bool ok = true;
    #pragma unroll
    for (int i = 0; i < 4; i++) {
        long long v = __ldg(&q[i]);
        if (v < 0 || v >= N) ok = false;
    }
    return ok;
}

__device__ __forceinline__ int load_idx(const void* p, int i, bool e64, int N) {
    long long v = e64 ? ((const long long*)p)[i] : (long long)((const int*)p)[i];
    if (v < 0) v = 0;
    if (v >= N) v = N - 1;   // clamp: bad data -> rel_err, not a crash
    return (int)v;
}

// ---------------------------------------------------------------------------
// CSR build: zero -> histogram -> scan -> fill   (2 edges/thread for ILP)
// ---------------------------------------------------------------------------
__global__ void k_zero_cnt(int N) {
    int i = blockIdx.x * blockDim.x + threadIdx.x;
    if (i < N) g_cnt[i] = 0;
}

__global__ void k_hist(const void* __restrict__ dst, int E, int N) {
    int e = (blockIdx.x * blockDim.x + threadIdx.x) * 2;
    if (e >= E) return;
    bool e64 = detect_i64(dst, N);
    int d0 = load_idx(dst, e, e64, N);
    atomicAdd(&g_cnt[d0], 1);
    if (e + 1 < E) {
        int d1 = load_idx(dst, e + 1, e64, N);
        atomicAdd(&g_cnt[d1], 1);
    }
}

// single block, 1024 threads: per-thread serial sums + Hillis-Steele scan
__global__ void k_scan(int N) {
    __shared__ int ps[1024];
    int t = threadIdx.x;
    int C = (N + 1023) >> 10;
    int lo = t * C;
    int hi = lo + C; if (hi > N) hi = N;
    int s = 0;
    for (int i = lo; i < hi; i++) s += g_cnt[i];
    ps[t] = s;
    __syncthreads();
    #pragma unroll
    for (int off = 1; off < 1024; off <<= 1) {
        int v = (t >= off) ? ps[t - off] : 0;
        __syncthreads();
        ps[t] += v;
        __syncthreads();
    }
    int run = ps[t] - s;   // exclusive prefix
    for (int i = lo; i < hi; i++) {
        g_off[i] = run;
        g_cur[i] = run;
        run += g_cnt[i];
    }
    if (t == 1023) g_off[N] = ps[1023];
}

__global__ void k_fill(const void* __restrict__ src,
                       const void* __restrict__ dst, int E, int N) {
    int e = (blockIdx.x * blockDim.x + threadIdx.x) * 2;
    if (e >= E) return;
    bool e64 = detect_i64(src, N);
    int s0 = load_idx(src, e, e64, N);
    int d0 = load_idx(dst, e, e64, N);
    int s1 = 0, d1 = -1;
    if (e + 1 < E) {
        s1 = load_idx(src, e + 1, e64, N);
        d1 = load_idx(dst, e + 1, e64, N);
    }
    int p0 = atomicAdd(&g_cur[d0], 1);
    if (d1 >= 0) {
        int p1 = atomicAdd(&g_cur[d1], 1);
        g_eidx[p1] = s1;
    }
    g_eidx[p0] = s0;
}

// ---------------------------------------------------------------------------
// FUSED kernel:  per warp, 4 nodes:
//   Phase A: gather-sum feature[src] for each node directly into smem rowbuf
//   Phase B: rowbuf @ W^T -> snorm -> layernorm -> relu -> out
// h never touches global memory.
// ---------------------------------------------------------------------------
__global__ __launch_bounds__(256, 2) void k_fused(
    const float* __restrict__ feat,   // [N,D]
    const float* __restrict__ Wg,     // [D,D] row-major: W[j*D+k]
    const float* __restrict__ snorm,  // [N]
    const float* __restrict__ gamma,  // [D]
    const float* __restrict__ beta,   // [D]
    float* __restrict__ out,          // [N,D]
    int N, int use_csr)
{
    extern __shared__ float sm[];
    float* Wt = sm;                   // Wt[k*128 + j] = W[j][k]
    float* rowbuf = sm + DD * DD;     // 8 warps * 4 rows * 128 floats

    for (int idx = threadIdx.x; idx < DD * DD; idx += blockDim.x) {
        int j = idx >> 7;
        int k = idx & 127;
        Wt[k * DD + j] = Wg[idx];
    }
    __syncthreads();

    const int warp = threadIdx.x >> 5;
    const int lane = threadIdx.x & 31;
    const float4 gm = reinterpret_cast<const float4*>(gamma)[lane];
    const float4 bt = reinterpret_cast<const float4*>(beta)[lane];
    float* rb = rowbuf + warp * (4 * DD);
    const float4* Wt4 = reinterpret_cast<const float4*>(Wt);
    const float4* f4 = reinterpret_cast<const float4*>(feat);

    for (int row0 = blockIdx.x * 32 + warp * 4; row0 < N;
         row0 += gridDim.x * 32) {

        // ---- Phase A: aggregate 4 rows into smem ----
        #pragma unroll
        for (int r = 0; r < 4; r++) {
            int row = row0 + r;
            if (row >= N) row = N - 1;  // clamp (results discarded)
            float4 a0 = make_float4(0.f, 0.f, 0.f, 0.f);
            float4 a1 = make_float4(0.f, 0.f, 0.f, 0.f);
            if (use_csr) {
                int j   = __ldg(&g_off[row]);
                int end = __ldg(&g_off[row + 1]);
                for (; j + 4 <= end; j += 4) {
                    int s0 = __ldg(&g_eidx[j + 0]);
                    int s1 = __ldg(&g_eidx[j + 1]);
                    int s2 = __ldg(&g_eidx[j + 2]);
                    int s3 = __ldg(&g_eidx[j + 3]);
                    float4 v0 = f4[(size_t)s0 * 32 + lane];
                    float4 v1 = f4[(size_t)s1 * 32 + lane];
                    float4 v2 = f4[(size_t)s2 * 32 + lane];
                    float4 v3 = f4[(size_t)s3 * 32 + lane];
                    a0.x += v0.x; a0.y += v0.y; a0.z += v0.z; a0.w += v0.w;
                    a1.x += v1.x; a1.y += v1.y; a1.z += v1.z; a1.w += v1.w;
                    a0.x += v2.x; a0.y += v2.y; a0.z += v2.z; a0.w += v2.w;
                    a1.x += v3.x; a1.y += v3.y; a1.z += v3.z; a1.w += v3.w;
                }
                for (; j < end; j++) {
                    int s0 = __ldg(&g_eidx[j]);
                    float4 v0 = f4[(size_t)s0 * 32 + lane];
                    a0.x += v0.x; a0.y += v0.y; a0.z += v0.z; a0.w += v0.w;
                }
                a0.x += a1.x; a0.y += a1.y; a0.z += a1.z; a0.w += a1.w;
            } else {
                a0 = g_h4[(size_t)row * 32 + lane];  // fallback: precomputed
            }
            reinterpret_cast<float4*>(rb)[r * 32 + lane] = a0;
        }
        __syncwarp();

        // ---- Phase B: GEMM + norm epilogue ----
        float acc[4][4];
        #pragma unroll
        for (int r = 0; r < 4; r++)
            #pragma unroll
            for (int u = 0; u < 4; u++) acc[r][u] = 0.f;

        #pragma unroll 4
        for (int k = 0; k < DD; k += 4) {
            float4 a0 = *reinterpret_cast<const float4*>(rb + 0 * DD + k);
            float4 a1 = *reinterpret_cast<const float4*>(rb + 1 * DD + k);
            float4 a2 = *reinterpret_cast<const float4*>(rb + 2 * DD + k);
            float4 a3 = *reinterpret_cast<const float4*>(rb + 3 * DD + k);
            #pragma unroll
            for (int kk = 0; kk < 4; kk++) {
                float4 w = Wt4[(k + kk) * 32 + lane];
                float av0 = (&a0.x)[kk];
                float av1 = (&a1.x)[kk];
                float av2 = (&a2.x)[kk];
                float av3 = (&a3.x)[kk];
                acc[0][0] += av0 * w.x; acc[0][1] += av0 * w.y;
                acc[0][2] += av0 * w.z; acc[0][3] += av0 * w.w;
                acc[1][0] += av1 * w.x; acc[1][1] += av1 * w.y;
                acc[1][2] += av1 * w.z; acc[1][3] += av1 * w.w;
                acc[2][0] += av2 * w.x; acc[2][1] += av2 * w.y;
                acc[2][2] += av2 * w.z; acc[2][3] += av2 * w.w;
                acc[3][0] += av3 * w.x; acc[3][1] += av3 * w.y;
                acc[3][2] += av3 * w.z; acc[3][3] += av3 * w.w;
            }
        }

        #pragma unroll
        for (int r = 0; r < 4; r++) {
            int row = row0 + r;
            if (row >= N) break;
            float s = __ldg(snorm + row);
            float x0 = acc[r][0] * s, x1 = acc[r][1] * s;
            float x2 = acc[r][2] * s, x3 = acc[r][3] * s;
            float sum = x0 + x1 + x2 + x3;
            float sq  = x0 * x0 + x1 * x1 + x2 * x2 + x3 * x3;
            #pragma unroll
            for (int o = 16; o > 0; o >>= 1) {
                sum += __shfl_xor_sync(0xffffffffu, sum, o);
                sq  += __shfl_xor_sync(0xffffffffu, sq,  o);
            }
            float mean = sum * (1.0f / 128.0f);
            float var  = sq  * (1.0f / 128.0f) - mean * mean;
            float rstd = rsqrtf(var + 1e-5f);
            float4 o4;
            o4.x = fmaxf((x0 - mean) * rstd * gm.x + bt.x, 0.f);
            o4.y = fmaxf((x1 - mean) * rstd * gm.y + bt.y, 0.f);
            o4.z = fmaxf((x2 - mean) * rstd * gm.z + bt.z, 0.f);
            o4.w = fmaxf((x3 - mean) * rstd * gm.w + bt.w, 0.f);
            reinterpret_cast<float4*>(out)[(size_t)row * 32 + lane] = o4;
        }
        __syncwarp();
    }
}

// ---------------------------------------------------------------------------
// Fallback path (E > CAP_E): zero + vector reduction atomics into g_h4
// ---------------------------------------------------------------------------
__global__ void k_zero_h(int n4) {
    int i = blockIdx.x * blockDim.x + threadIdx.x;
    if (i < n4) g_h4[i] = make_float4(0.f, 0.f, 0.f, 0.f);
}

__global__ void k_scatter(const float* __restrict__ feat,
                          const void* __restrict__ src,
                          const void* __restrict__ dst,
                          int E, int N) {
    int gid = blockIdx.x * blockDim.x + threadIdx.x;
    int e = gid >> 5;
    int c = gid & 31;
    if (e >= E) return;
    bool e64 = detect_i64(src, N);
    int s = load_idx(src, e, e64, N);
    int d = load_idx(dst, e, e64, N);
    float4 v = reinterpret_cast<const float4*>(feat)[(size_t)s * 32 + c];
    float4* p = g_h4 + (size_t)d * 32 + c;
    asm volatile("red.global.add.v4.f32 [%0], {%1,%2,%3,%4};"
                 :: "l"(p), "f"(v.x), "f"(v.y), "f"(v.z), "f"(v.w)
                 : "memory");
}

// ---------------------------------------------------------------------------
extern "C" void kernel_launch(void* const* d_in, const int* in_sizes, int n_in,
                              void* d_out, int out_size) {
    const float* feature = (const float*)d_in[0];
    const float* snorm   = (const float*)d_in[1];
    const float* Wg      = (const float*)d_in[2];
    const float* gamma   = (const float*)d_in[3];
    const float* beta    = (const float*)d_in[4];
    const void*  src     = d_in[5];
    const void*  dst     = d_in[6];
    int N = in_sizes[1];            // snorm_n has N elements
    int E = in_sizes[5];
    float* out = (float*)d_out;

    int use_csr = (E <= CAP_E && N <= N_MAX) ? 1 : 0;

    if (use_csr) {
        k_zero_cnt<<<(N + 255) / 256, 256>>>(N);
        int ht = (E + 1) / 2;
        k_hist<<<(ht + 255) / 256, 256>>>(dst, E, N);
        k_scan<<<1, 1024>>>(N);
        k_fill<<<(ht + 255) / 256, 256>>>(src, dst, E, N);
    } else {
        int n4 = N * (DD / 4);
        k_zero_h<<<(n4 + 255) / 256, 256>>>(n4);
        long long tt = (long long)E * 32;
        k_scatter<<<(int)((tt + 255) / 256), 256>>>(feature, src, dst, E, N);
    }

    // fused aggregate + GEMM + graphnorm + layernorm + relu
    const int SMEM = (DD * DD + 8 * 4 * DD) * (int)sizeof(float);  // 80 KB
    cudaFuncSetAttribute(k_fused,
                         cudaFuncAttributeMaxDynamicSharedMemorySize, SMEM);
    k_fused<<<296, 256, SMEM>>>(feature, Wg, snorm, gamma, beta, out, N, use_csr);
}

// round 6
// speedup vs baseline: 1.3057x; 1.3057x over previous
#include <cuda_runtime.h>
#include <cstdint>

#define DD 128
#define N_MAX 50000

// scratch: aggregated features h = segment_sum(feature[src], dst)
static __device__ float4 g_h4[(size_t)N_MAX * (DD / 4)];

// ---------------------------------------------------------------------------
// Index dtype detection: reference declares int64 indices but JAX with x64
// disabled emits int32. First 4 elements viewed as int64 land in [0,N) only
// if the data really is int64.
// ---------------------------------------------------------------------------
__device__ __forceinline__ bool detect_i64(const void* p, int N) {
    const long long* q = (const long long*)p;
    bool ok = true;
    #pragma unroll
    for (int i = 0; i < 4; i++) {
        long long v = __ldg(&q[i]);
        if (v < 0 || v >= N) ok = false;
    }
    return ok;
}

__device__ __forceinline__ int load_idx(const void* p, int i, bool e64, int N) {
    long long v = e64 ? ((const long long*)p)[i] : (long long)((const int*)p)[i];
    if (v < 0) v = 0;
    if (v >= N) v = N - 1;   // clamp: bad data -> rel_err, not a crash
    return (int)v;
}

// ---------------------------------------------------------------------------
// Kernel 1: zero the accumulator (4 float4 per thread)
// ---------------------------------------------------------------------------
__global__ void k_zero(int n4) {
    int i = (blockIdx.x * blockDim.x + threadIdx.x) * 4;
    float4 z = make_float4(0.f, 0.f, 0.f, 0.f);
    if (i + 3 < n4) {
        g_h4[i + 0] = z; g_h4[i + 1] = z; g_h4[i + 2] = z; g_h4[i + 3] = z;
    } else {
        for (int k = i; k < n4; k++) g_h4[k] = z;
    }
}

// ---------------------------------------------------------------------------
// Kernel 2: gather + scatter-add. Each warp handles TWO edges; lane c owns
// float4 column c of both. Two independent gathers + two vec4 reduction
// atomics in flight per thread for latency hiding.
// ---------------------------------------------------------------------------
__global__ void k_scatter(const float* __restrict__ feat,
                          const void* __restrict__ src,
                          const void* __restrict__ dst,
                          int E, int N) {
    int gid = blockIdx.x * blockDim.x + threadIdx.x;
    int w = gid >> 5;            // warp index -> edge pair
    int c = gid & 31;            // float4 column
    int e0 = w * 2;
    int e1 = e0 + 1;
    if (e0 >= E) return;
    bool e64 = detect_i64(src, N);     // warp-uniform broadcast loads
    const float4* f4 = reinterpret_cast<const float4*>(feat);

    int s0 = load_idx(src, e0, e64, N);
    int d0 = load_idx(dst, e0, e64, N);
    if (e1 < E) {
        int s1 = load_idx(src, e1, e64, N);
        int d1 = load_idx(dst, e1, e64, N);
        float4 v0 = f4[(size_t)s0 * 32 + c];
        float4 v1 = f4[(size_t)s1 * 32 + c];
        float4* p0 = g_h4 + (size_t)d0 * 32 + c;
        float4* p1 = g_h4 + (size_t)d1 * 32 + c;
        asm volatile("red.global.add.v4.f32 [%0], {%1,%2,%3,%4};"
                     :: "l"(p0), "f"(v0.x), "f"(v0.y), "f"(v0.z), "f"(v0.w)
                     : "memory");
        asm volatile("red.global.add.v4.f32 [%0], {%1,%2,%3,%4};"
                     :: "l"(p1), "f"(v1.x), "f"(v1.y), "f"(v1.z), "f"(v1.w)
                     : "memory");
    } else {
        float4 v0 = f4[(size_t)s0 * 32 + c];
        float4* p0 = g_h4 + (size_t)d0 * 32 + c;
        asm volatile("red.global.add.v4.f32 [%0], {%1,%2,%3,%4};"
                     :: "l"(p0), "f"(v0.x), "f"(v0.y), "f"(v0.z), "f"(v0.w)
                     : "memory");
    }
}

// ---------------------------------------------------------------------------
// Kernel 3: fused  out = relu(layernorm((h @ W^T) * snorm) * gamma + beta)
// 8-row register blocking per warp: 12 LDS.128 per 128 FFMA -> cleanly
// FFMA-issue bound (smem crossbar at 96 B/cyc < 128 B/cyc cap).
// ---------------------------------------------------------------------------
__global__ __launch_bounds__(256, 2) void k_gemm_norm(
    const float* __restrict__ snorm,  // [N]
    const float* __restrict__ Wg,     // [D,D] row-major: W[j*D+k]
    const float* __restrict__ gamma,  // [D]
    const float* __restrict__ beta,   // [D]
    float* __restrict__ out,          // [N,D]
    int N)
{
    extern __shared__ float sm[];
    float* Wt = sm;                   // 16384 floats: Wt[k*128 + j] = W[j][k]
    float* rowbuf = sm + DD * DD;     // 8 warps * 8 rows * 128 floats = 32KB

    // load + transpose W into smem (coalesced global reads)
    for (int idx = threadIdx.x; idx < DD * DD; idx += blockDim.x) {
        int j = idx >> 7;
        int k = idx & 127;
        Wt[k * DD + j] = Wg[idx];
    }
    __syncthreads();

    const int warp = threadIdx.x >> 5;
    const int lane = threadIdx.x & 31;
    const float4 gm = reinterpret_cast<const float4*>(gamma)[lane];
    const float4 bt = reinterpret_cast<const float4*>(beta)[lane];
    float* rb = rowbuf + warp * (8 * DD);
    const float4* Wt4 = reinterpret_cast<const float4*>(Wt);

    for (int row0 = blockIdx.x * 64 + warp * 8; row0 < N;
         row0 += gridDim.x * 64) {

        // stage this warp's 8 rows of h into smem
        #pragma unroll
        for (int r = 0; r < 8; r++) {
            int row = row0 + r;
            if (row >= N) row = N - 1;  // clamp (results discarded)
            reinterpret_cast<float4*>(rb)[r * 32 + lane] =
                g_h4[(size_t)row * 32 + lane];
        }
        __syncwarp();

        float acc[8][4];
        #pragma unroll
        for (int r = 0; r < 8; r++)
            #pragma unroll
            for (int u = 0; u < 4; u++) acc[r][u] = 0.f;

        #pragma unroll 2
        for (int k = 0; k < DD; k += 4) {
            float4 a[8];
            #pragma unroll
            for (int r = 0; r < 8; r++)
                a[r] = *reinterpret_cast<const float4*>(rb + r * DD + k);
            #pragma unroll
            for (int kk = 0; kk < 4; kk++) {
                float4 w = Wt4[(k + kk) * 32 + lane];
                #pragma unroll
                for (int r = 0; r < 8; r++) {
                    float av = (&a[r].x)[kk];
                    acc[r][0] += av * w.x;
                    acc[r][1] += av * w.y;
                    acc[r][2] += av * w.z;
                    acc[r][3] += av * w.w;
                }
            }
        }

        // fused epilogue: snorm scale -> layernorm -> affine -> relu
        #pragma unroll
        for (int r = 0; r < 8; r++) {
            int row = row0 + r;
            if (row >= N) break;
            float s = __ldg(snorm + row);
            float x0 = acc[r][0] * s, x1 = acc[r][1] * s;
            float x2 = acc[r][2] * s, x3 = acc[r][3] * s;
            float sum = x0 + x1 + x2 + x3;
            float sq  = x0 * x0 + x1 * x1 + x2 * x2 + x3 * x3;
            #pragma unroll
            for (int o = 16; o > 0; o >>= 1) {
                sum += __shfl_xor_sync(0xffffffffu, sum, o);
                sq  += __shfl_xor_sync(0xffffffffu, sq,  o);
            }
            float mean = sum * (1.0f / 128.0f);
            float var  = sq  * (1.0f / 128.0f) - mean * mean;
            float rstd = rsqrtf(var + 1e-5f);
            float4 o4;
            o4.x = fmaxf((x0 - mean) * rstd * gm.x + bt.x, 0.f);
            o4.y = fmaxf((x1 - mean) * rstd * gm.y + bt.y, 0.f);
            o4.z = fmaxf((x2 - mean) * rstd * gm.z + bt.z, 0.f);
            o4.w = fmaxf((x3 - mean) * rstd * gm.w + bt.w, 0.f);
            reinterpret_cast<float4*>(out)[(size_t)row * 32 + lane] = o4;
        }
        __syncwarp();
    }
}

// ---------------------------------------------------------------------------
extern "C" void kernel_launch(void* const* d_in, const int* in_sizes, int n_in,
                              void* d_out, int out_size) {
    const float* feature = (const float*)d_in[0];
    const float* snorm   = (const float*)d_in[1];
    const float* Wg      = (const float*)d_in[2];
    const float* gamma   = (const float*)d_in[3];
    const float* beta    = (const float*)d_in[4];
    const void*  src     = d_in[5];
    const void*  dst     = d_in[6];
    int N = in_sizes[1];            // snorm_n has N elements
    int E = in_sizes[5];
    float* out = (float*)d_out;

    // 1) zero accumulator
    int n4 = N * (DD / 4);
    int zthreads = (n4 + 3) / 4;
    k_zero<<<(zthreads + 255) / 256, 256>>>(n4);

    // 2) gather + vector-atomic scatter: one warp per TWO edges
    int npairs = (E + 1) / 2;
    long long tt = (long long)npairs * 32;
    k_scatter<<<(int)((tt + 255) / 256), 256>>>(feature, src, dst, E, N);

    // 3) fused GEMM + graphnorm + layernorm + relu (8-row warp tiles)
    const int SMEM = (DD * DD + 8 * 8 * DD) * (int)sizeof(float);  // 96 KB
    cudaFuncSetAttribute(k_gemm_norm,
                         cudaFuncAttributeMaxDynamicSharedMemorySize, SMEM);
    k_gemm_norm<<<296, 256, SMEM>>>(snorm, Wg, gamma, beta, out, N);
}

// round 7
// speedup vs baseline: 1.3756x; 1.0536x over previous
#include <cuda_runtime.h>
#include <cstdint>

#define DD 128
#define N_MAX 50000

// scratch: aggregated features h = segment_sum(feature[src], dst)
static __device__ float4 g_h4[(size_t)N_MAX * (DD / 4)];

// ---------------------------------------------------------------------------
// Index dtype detection: reference declares int64 indices but JAX with x64
// disabled emits int32. First 4 elements viewed as int64 land in [0,N) only
// if the data really is int64.
// ---------------------------------------------------------------------------
__device__ __forceinline__ bool detect_i64(const void* p, int N) {
    const long long* q = (const long long*)p;
    bool ok = true;
    #pragma unroll
    for (int i = 0; i < 4; i++) {
        long long v = __ldg(&q[i]);
        if (v < 0 || v >= N) ok = false;
    }
    return ok;
}

__device__ __forceinline__ int load_idx(const void* p, int i, bool e64, int N) {
    long long v = e64 ? ((const long long*)p)[i] : (long long)((const int*)p)[i];
    if (v < 0) v = 0;
    if (v >= N) v = N - 1;   // clamp: bad data -> rel_err, not a crash
    return (int)v;
}

// ---------------------------------------------------------------------------
// packed f32x2 FMA (Blackwell FFMA2) + unpack helpers
// ---------------------------------------------------------------------------
__device__ __forceinline__ void fma2(unsigned long long& d,
                                     unsigned long long a,
                                     unsigned long long b) {
    asm("fma.rn.f32x2 %0, %1, %2, %0;" : "+l"(d) : "l"(a), "l"(b));
}
__device__ __forceinline__ float ull_lo(unsigned long long v) {
    return __uint_as_float((unsigned)v);
}
__device__ __forceinline__ float ull_hi(unsigned long long v) {
    return __uint_as_float((unsigned)(v >> 32));
}

// ---------------------------------------------------------------------------
// Kernel: gather + scatter-add. Each warp handles FOUR edges; lane c owns
// float4 column c. 4 independent gather+RED chains per thread for MLP.
// ---------------------------------------------------------------------------
__global__ void k_scatter(const float* __restrict__ feat,
                          const void* __restrict__ src,
                          const void* __restrict__ dst,
                          int E, int N) {
    int gid = blockIdx.x * blockDim.x + threadIdx.x;
    int w = gid >> 5;
    int c = gid & 31;
    int e0 = w * 4;
    if (e0 >= E) return;
    bool e64 = detect_i64(src, N);     // warp-uniform broadcast loads
    const float4* f4 = reinterpret_cast<const float4*>(feat);

    if (e0 + 3 < E) {
        int s0 = load_idx(src, e0 + 0, e64, N), d0 = load_idx(dst, e0 + 0, e64, N);
        int s1 = load_idx(src, e0 + 1, e64, N), d1 = load_idx(dst, e0 + 1, e64, N);
        int s2 = load_idx(src, e0 + 2, e64, N), d2 = load_idx(dst, e0 + 2, e64, N);
        int s3 = load_idx(src, e0 + 3, e64, N), d3 = load_idx(dst, e0 + 3, e64, N);
        float4 v0 = f4[(size_t)s0 * 32 + c];
        float4 v1 = f4[(size_t)s1 * 32 + c];
        float4 v2 = f4[(size_t)s2 * 32 + c];
        float4 v3 = f4[(size_t)s3 * 32 + c];
        float4* p0 = g_h4 + (size_t)d0 * 32 + c;
        float4* p1 = g_h4 + (size_t)d1 * 32 + c;
        float4* p2 = g_h4 + (size_t)d2 * 32 + c;
        float4* p3 = g_h4 + (size_t)d3 * 32 + c;
        asm volatile("red.global.add.v4.f32 [%0], {%1,%2,%3,%4};"
                     :: "l"(p0), "f"(v0.x), "f"(v0.y), "f"(v0.z), "f"(v0.w) : "memory");
        asm volatile("red.global.add.v4.f32 [%0], {%1,%2,%3,%4};"
                     :: "l"(p1), "f"(v1.x), "f"(v1.y), "f"(v1.z), "f"(v1.w) : "memory");
        asm volatile("red.global.add.v4.f32 [%0], {%1,%2,%3,%4};"
                     :: "l"(p2), "f"(v2.x), "f"(v2.y), "f"(v2.z), "f"(v2.w) : "memory");
        asm volatile("red.global.add.v4.f32 [%0], {%1,%2,%3,%4};"
                     :: "l"(p3), "f"(v3.x), "f"(v3.y), "f"(v3.z), "f"(v3.w) : "memory");
    } else {
        for (int e = e0; e < E; e++) {
            int s = load_idx(src, e, e64, N);
            int d = load_idx(dst, e, e64, N);
            float4 v = f4[(size_t)s * 32 + c];
            float4* p = g_h4 + (size_t)d * 32 + c;
            asm volatile("red.global.add.v4.f32 [%0], {%1,%2,%3,%4};"
                         :: "l"(p), "f"(v.x), "f"(v.y), "f"(v.z), "f"(v.w) : "memory");
        }
    }
}

// ---------------------------------------------------------------------------
// Fused  out = relu(layernorm((h @ W^T) * snorm) * gamma + beta)
// FFMA2 mainloop: accumulators hold (even-k partial, odd-k partial) packed
// f32x2; folded in the epilogue. W staged in smem as two planes
// [kp][lane][4 floats] so LDS.128 is lane-consecutive (conflict-free).
// ---------------------------------------------------------------------------
__global__ __launch_bounds__(256, 2) void k_gemm_norm(
    const float* __restrict__ snorm,  // [N]
    const float* __restrict__ Wg,     // [D,D] row-major: W[j*D+k]
    const float* __restrict__ gamma,  // [D]
    const float* __restrict__ beta,   // [D]
    float* __restrict__ out,          // [N,D]
    int N)
{
    extern __shared__ float sm[];
    float* WtpA  = sm;                 // 8192 floats: j%4 in {0,1} plane
    float* WtpB  = sm + 8192;          // 8192 floats: j%4 in {2,3} plane
    float* rowbuf = sm + 16384;        // 8 warps * 8 rows * 128 floats = 32KB

    // Stage W: WtpX[kp*128 + ln*4 + jm2*2 + par] = W[j][2kp+par]
    // where j = 4*ln + (plane? jm2+2 : jm2). Coalesced global reads.
    for (int idx = threadIdx.x; idx < DD * DD; idx += blockDim.x) {
        int j = idx >> 7;
        int k = idx & 127;
        int kp = k >> 1, par = k & 1;
        int ln = j >> 2, jm = j & 3;
        float v = Wg[idx];
        if (jm < 2) WtpA[kp * 128 + ln * 4 + jm * 2 + par] = v;
        else        WtpB[kp * 128 + ln * 4 + (jm - 2) * 2 + par] = v;
    }
    __syncthreads();

    const int warp = threadIdx.x >> 5;
    const int lane = threadIdx.x & 31;
    const float4 gm = reinterpret_cast<const float4*>(gamma)[lane];
    const float4 bt = reinterpret_cast<const float4*>(beta)[lane];
    float* rb = rowbuf + warp * (8 * DD);
    const unsigned long long* rb8 = reinterpret_cast<const unsigned long long*>(rb);
    const ulonglong2* WA2 = reinterpret_cast<const ulonglong2*>(WtpA);
    const ulonglong2* WB2 = reinterpret_cast<const ulonglong2*>(WtpB);

    for (int row0 = blockIdx.x * 64 + warp * 8; row0 < N;
         row0 += gridDim.x * 64) {

        // stage this warp's 8 rows of h into smem
        #pragma unroll
        for (int r = 0; r < 8; r++) {
            int row = row0 + r;
            if (row >= N) row = N - 1;  // clamp (results discarded)
            reinterpret_cast<float4*>(rb)[r * 32 + lane] =
                g_h4[(size_t)row * 32 + lane];
        }
        __syncwarp();

        // acc2[r][u]: packed (even-k, odd-k) partial sums for output col u
        unsigned long long acc2[8][4];
        #pragma unroll
        for (int r = 0; r < 8; r++)
            #pragma unroll
            for (int u = 0; u < 4; u++) acc2[r][u] = 0ull;

        #pragma unroll 4
        for (int kp = 0; kp < 64; kp++) {
            ulonglong2 wA = WA2[kp * 32 + lane];  // (w2[j0], w2[j1])
            ulonglong2 wB = WB2[kp * 32 + lane];  // (w2[j2], w2[j3])
            #pragma unroll
            for (int r = 0; r < 8; r++) {
                unsigned long long a2 = rb8[r * 64 + kp];  // broadcast LDS.64
                fma2(acc2[r][0], a2, wA.x);
                fma2(acc2[r][1], a2, wA.y);
                fma2(acc2[r][2], a2, wB.x);
                fma2(acc2[r][3], a2, wB.y);
            }
        }

        // epilogue: fold pairs -> snorm scale -> layernorm -> affine -> relu
        #pragma unroll
        for (int r = 0; r < 8; r++) {
            int row = row0 + r;
            if (row >= N) break;
            float s = __ldg(snorm + row);
            float x0 = (ull_lo(acc2[r][0]) + ull_hi(acc2[r][0])) * s;
            float x1 = (ull_lo(acc2[r][1]) + ull_hi(acc2[r][1])) * s;
            float x2 = (ull_lo(acc2[r][2]) + ull_hi(acc2[r][2])) * s;
            float x3 = (ull_lo(acc2[r][3]) + ull_hi(acc2[r][3])) * s;
            float sum = x0 + x1 + x2 + x3;
            float sq  = x0 * x0 + x1 * x1 + x2 * x2 + x3 * x3;
            #pragma unroll
            for (int o = 16; o > 0; o >>= 1) {
                sum += __shfl_xor_sync(0xffffffffu, sum, o);
                sq  += __shfl_xor_sync(0xffffffffu, sq,  o);
            }
            float mean = sum * (1.0f / 128.0f);
            float var  = sq  * (1.0f / 128.0f) - mean * mean;
            float rstd = rsqrtf(var + 1e-5f);
            float4 o4;
            o4.x = fmaxf((x0 - mean) * rstd * gm.x + bt.x, 0.f);
            o4.y = fmaxf((x1 - mean) * rstd * gm.y + bt.y, 0.f);
            o4.z = fmaxf((x2 - mean) * rstd * gm.z + bt.z, 0.f);
            o4.w = fmaxf((x3 - mean) * rstd * gm.w + bt.w, 0.f);
            reinterpret_cast<float4*>(out)[(size_t)row * 32 + lane] = o4;
        }
        __syncwarp();
    }
}

// ---------------------------------------------------------------------------
extern "C" void kernel_launch(void* const* d_in, const int* in_sizes, int n_in,
                              void* d_out, int out_size) {
    const float* feature = (const float*)d_in[0];
    const float* snorm   = (const float*)d_in[1];
    const float* Wg      = (const float*)d_in[2];
    const float* gamma   = (const float*)d_in[3];
    const float* beta    = (const float*)d_in[4];
    const void*  src     = d_in[5];
    const void*  dst     = d_in[6];
    int N = in_sizes[1];            // snorm_n has N elements
    int E = in_sizes[5];
    float* out = (float*)d_out;

    // 1) zero accumulator via async memset (graph-capturable memset node)
    void* hptr = nullptr;
    cudaGetSymbolAddress(&hptr, g_h4);
    cudaMemsetAsync(hptr, 0, (size_t)N * DD * sizeof(float), 0);

    // 2) gather + vector-atomic scatter: one warp per FOUR edges
    int nq = (E + 3) / 4;
    long long tt = (long long)nq * 32;
    k_scatter<<<(int)((tt + 255) / 256), 256>>>(feature, src, dst, E, N);

    // 3) fused GEMM (FFMA2) + graphnorm + layernorm + relu
    const int SMEM = (DD * DD + 8 * 8 * DD) * (int)sizeof(float);  // 96 KB
    cudaFuncSetAttribute(k_gemm_norm,
                         cudaFuncAttributeMaxDynamicSharedMemorySize, SMEM);
    k_gemm_norm<<<296, 256, SMEM>>>(snorm, Wg, gamma, beta, out, N);
}

// round 9
// speedup vs baseline: 1.8107x; 1.3162x over previous
#include <cuda_runtime.h>
#include <cuda_bf16.h>
#include <cstdint>

#define DD 128
#define N_MAX 50000

// scratch: aggregated features h = segment_sum(feature[src], dst)
static __device__ float4 g_h4[(size_t)N_MAX * (DD / 4)];

// ---------------------------------------------------------------------------
// Index dtype detection (reference says int64, JAX x64-off emits int32)
// ---------------------------------------------------------------------------
__device__ __forceinline__ bool detect_i64(const void* p, int N) {
    const long long* q = (const long long*)p;
    bool ok = true;
    #pragma unroll
    for (int i = 0; i < 4; i++) {
        long long v = __ldg(&q[i]);
        if (v < 0 || v >= N) ok = false;
    }
    return ok;
}

__device__ __forceinline__ int load_idx(const void* p, int i, bool e64, int N) {
    long long v = e64 ? ((const long long*)p)[i] : (long long)((const int*)p)[i];
    if (v < 0) v = 0;
    if (v >= N) v = N - 1;
    return (int)v;
}

// ---------------------------------------------------------------------------
// Scatter: one warp per FOUR edges, lane c owns float4 column c.
// ---------------------------------------------------------------------------
__global__ void k_scatter(const float* __restrict__ feat,
                          const void* __restrict__ src,
                          const void* __restrict__ dst,
                          int E, int N) {
    int gid = blockIdx.x * blockDim.x + threadIdx.x;
    int w = gid >> 5;
    int c = gid & 31;
    int e0 = w * 4;
    if (e0 >= E) return;
    bool e64 = detect_i64(src, N);
    const float4* f4 = reinterpret_cast<const float4*>(feat);

    if (e0 + 3 < E) {
        int s0 = load_idx(src, e0 + 0, e64, N), d0 = load_idx(dst, e0 + 0, e64, N);
        int s1 = load_idx(src, e0 + 1, e64, N), d1 = load_idx(dst, e0 + 1, e64, N);
        int s2 = load_idx(src, e0 + 2, e64, N), d2 = load_idx(dst, e0 + 2, e64, N);
        int s3 = load_idx(src, e0 + 3, e64, N), d3 = load_idx(dst, e0 + 3, e64, N);
        float4 v0 = f4[(size_t)s0 * 32 + c];
        float4 v1 = f4[(size_t)s1 * 32 + c];
        float4 v2 = f4[(size_t)s2 * 32 + c];
        float4 v3 = f4[(size_t)s3 * 32 + c];
        float4* p0 = g_h4 + (size_t)d0 * 32 + c;
        float4* p1 = g_h4 + (size_t)d1 * 32 + c;
        float4* p2 = g_h4 + (size_t)d2 * 32 + c;
        float4* p3 = g_h4 + (size_t)d3 * 32 + c;
        asm volatile("red.global.add.v4.f32 [%0], {%1,%2,%3,%4};"
                     :: "l"(p0), "f"(v0.x), "f"(v0.y), "f"(v0.z), "f"(v0.w) : "memory");
        asm volatile("red.global.add.v4.f32 [%0], {%1,%2,%3,%4};"
                     :: "l"(p1), "f"(v1.x), "f"(v1.y), "f"(v1.z), "f"(v1.w) : "memory");
        asm volatile("red.global.add.v4.f32 [%0], {%1,%2,%3,%4};"
                     :: "l"(p2), "f"(v2.x), "f"(v2.y), "f"(v2.z), "f"(v2.w) : "memory");
        asm volatile("red.global.add.v4.f32 [%0], {%1,%2,%3,%4};"
                     :: "l"(p3), "f"(v3.x), "f"(v3.y), "f"(v3.z), "f"(v3.w) : "memory");
    } else {
        for (int e = e0; e < E; e++) {
            int s = load_idx(src, e, e64, N);
            int d = load_idx(dst, e, e64, N);
            float4 v = f4[(size_t)s * 32 + c];
            float4* p = g_h4 + (size_t)d * 32 + c;
            asm volatile("red.global.add.v4.f32 [%0], {%1,%2,%3,%4};"
                         :: "l"(p), "f"(v.x), "f"(v.y), "f"(v.z), "f"(v.w) : "memory");
        }
    }
}

// ===========================================================================
// bf16 split mma.sync GEMM + fused graphnorm/layernorm/relu
// ===========================================================================

#define WSTRIDE 272                       // bytes per k-row (136 bf16): LDSM conflict-free
#define SM_GAMMA 0
#define SM_BETA  512
#define WH_OFF   1024
#define WL_OFF   (WH_OFF + 128 * WSTRIDE) // 35840
#define A_OFF    (WL_OFF + 128 * WSTRIDE) // 70656
#define A_WARP   (2 * 16 * WSTRIDE)       // 8704 per warp (hi+lo planes)
#define SM_TOTAL (A_OFF + 8 * A_WARP)     // 140288 bytes

__device__ __forceinline__ uint32_t smem_u32(const void* p) {
    uint32_t a;
    asm("{ .reg .u64 t; cvta.to.shared.u64 t, %1; cvt.u32.u64 %0, t; }"
        : "=r"(a) : "l"(p));
    return a;
}

__device__ __forceinline__ unsigned pk_bf16(float a, float b) {
    __nv_bfloat162 t = __floats2bfloat162_rn(a, b);   // .x=a(lo addr), .y=b
    return *reinterpret_cast<unsigned*>(&t);
}

// split (a,b) into packed hi-pair and lo-pair bf16x2
__device__ __forceinline__ void split2(float a, float b, unsigned& hi, unsigned& lo) {
    __nv_bfloat16 ha = __float2bfloat16_rn(a);
    __nv_bfloat16 hb = __float2bfloat16_rn(b);
    __nv_bfloat162 h = __halves2bfloat162(ha, hb);
    hi = *reinterpret_cast<unsigned*>(&h);
    lo = pk_bf16(a - __bfloat162float(ha), b - __bfloat162float(hb));
}

__device__ __forceinline__ void ldsm4(uint32_t addr, uint32_t r[4]) {
    asm volatile("ldmatrix.sync.aligned.m8n8.x4.shared.b16 {%0,%1,%2,%3}, [%4];"
                 : "=r"(r[0]), "=r"(r[1]), "=r"(r[2]), "=r"(r[3]) : "r"(addr));
}

__device__ __forceinline__ void mma_bf16(float d[4], const uint32_t a[4],
                                         uint32_t b0, uint32_t b1) {
    asm volatile(
        "mma.sync.aligned.m16n8k16.row.col.f32.bf16.bf16.f32 "
        "{%0,%1,%2,%3}, {%4,%5,%6,%7}, {%8,%9}, {%0,%1,%2,%3};"
        : "+f"(d[0]), "+f"(d[1]), "+f"(d[2]), "+f"(d[3])
        : "r"(a[0]), "r"(a[1]), "r"(a[2]), "r"(a[3]), "r"(b0), "r"(b1));
}

__global__ __launch_bounds__(256, 1) void k_mma_norm(
    const float* __restrict__ snorm,
    const float* __restrict__ Wg,     // [128,128] row-major W[j][k]
    const float* __restrict__ gamma,
    const float* __restrict__ beta,
    float* __restrict__ out,
    int N)
{
    extern __shared__ char smem[];
    uint32_t sb = smem_u32(smem);
    int tid = threadIdx.x;
    int lane = tid & 31;
    int warp = tid >> 5;

    if (tid < 128) {
        ((float*)(smem + SM_GAMMA))[tid] = gamma[tid];
        ((float*)(smem + SM_BETA))[tid]  = beta[tid];
    }

    // Stage W once: hi/lo bf16 planes, layout [j][k] (row j = output col).
    // As the B operand this is col-major k x n -> plain ldmatrix.
    {
        int j = tid >> 1, half = tid & 1;
        const float4* W4 = reinterpret_cast<const float4*>(Wg);
        #pragma unroll 4
        for (int q = 0; q < 16; q++) {
            float4 v = W4[j * 32 + half * 16 + q];
            int c0 = half * 64 + q * 4;          // k column
            unsigned h01, l01, h23, l23;
            split2(v.x, v.y, h01, l01);
            split2(v.z, v.w, h23, l23);
            uint2 uh; uh.x = h01; uh.y = h23;
            uint2 ul; ul.x = l01; ul.y = l23;
            *reinterpret_cast<uint2*>(smem + WH_OFF + j * WSTRIDE + c0 * 2) = uh;
            *reinterpret_cast<uint2*>(smem + WL_OFF + j * WSTRIDE + c0 * 2) = ul;
        }
    }
    __syncthreads();

    char* Ah = smem + A_OFF + warp * A_WARP;
    char* Al = Ah + 16 * WSTRIDE;
    uint32_t AhU = sb + A_OFF + warp * A_WARP;
    uint32_t AlU = AhU + 16 * WSTRIDE;

    // ldmatrix lane-address components (hoisted)
    const int arow  = (lane & 7) + ((lane >> 3) & 1) * 8;
    const int ahalf = (lane >> 4) & 1;                 // A: k-half select
    const int bn    = (lane & 7) + ((lane >> 4) & 1) * 8;  // B: n within pair
    const int bkh   = (lane >> 3) & 1;                 // B: k-half select

    const int ntiles = (N + 15) >> 4;

    for (int tile = blockIdx.x * 8 + warp; tile < ntiles; tile += gridDim.x * 8) {
        int row0 = tile * 16;

        // ---- stage A (16 rows) as hi/lo bf16 planes ----
        #pragma unroll 4
        for (int r = 0; r < 16; r++) {
            int row = row0 + r;
            if (row >= N) row = N - 1;
            float4 v = g_h4[(size_t)row * 32 + lane];   // cols 4*lane..+3
            unsigned h01, l01, h23, l23;
            split2(v.x, v.y, h01, l01);
            split2(v.z, v.w, h23, l23);
            uint2 uh; uh.x = h01; uh.y = h23;
            uint2 ul; ul.x = l01; ul.y = l23;
            *reinterpret_cast<uint2*>(Ah + r * WSTRIDE + lane * 8) = uh;
            *reinterpret_cast<uint2*>(Al + r * WSTRIDE + lane * 8) = ul;
        }
        __syncwarp();

        float acc[16][4];
        #pragma unroll
        for (int n = 0; n < 16; n++)
            #pragma unroll
            for (int u = 0; u < 4; u++) acc[n][u] = 0.f;

        #pragma unroll 1
        for (int ks = 0; ks < 8; ks++) {
            int k0 = ks * 16;
            uint32_t ah[4], al[4];
            uint32_t aoff = (uint32_t)(arow * WSTRIDE + (k0 + ahalf * 8) * 2);
            ldsm4(AhU + aoff, ah);
            ldsm4(AlU + aoff, al);
            #pragma unroll
            for (int p = 0; p < 8; p++) {
                int n = p * 16 + bn;
                uint32_t boff = (uint32_t)(n * WSTRIDE + (k0 + bkh * 8) * 2);
                uint32_t bh[4], bl[4];
                ldsm4(sb + WH_OFF + boff, bh);
                ldsm4(sb + WL_OFF + boff, bl);
                mma_bf16(acc[2 * p + 0], ah, bh[0], bh[1]);
                mma_bf16(acc[2 * p + 0], al, bh[0], bh[1]);
                mma_bf16(acc[2 * p + 0], ah, bl[0], bl[1]);
                mma_bf16(acc[2 * p + 1], ah, bh[2], bh[3]);
                mma_bf16(acc[2 * p + 1], al, bh[2], bh[3]);
                mma_bf16(acc[2 * p + 1], ah, bl[2], bl[3]);
            }
        }

        // ---- epilogue: snorm -> layernorm -> affine -> relu ----
        int r1 = row0 + (lane >> 2);
        int r2 = r1 + 8;
        float s1 = (r1 < N) ? __ldg(snorm + r1) : 0.f;
        float s2 = (r2 < N) ? __ldg(snorm + r2) : 0.f;
        float sum1 = 0.f, sq1 = 0.f, sum2 = 0.f, sq2 = 0.f;
        #pragma unroll
        for (int n = 0; n < 16; n++) {
            acc[n][0] *= s1; acc[n][1] *= s1;
            acc[n][2] *= s2; acc[n][3] *= s2;
            sum1 += acc[n][0] + acc[n][1];
            sq1  += acc[n][0] * acc[n][0] + acc[n][1] * acc[n][1];
            sum2 += acc[n][2] + acc[n][3];
            sq2  += acc[n][2] * acc[n][2] + acc[n][3] * acc[n][3];
        }
        #pragma unroll
        for (int o = 1; o <= 2; o <<= 1) {
            sum1 += __shfl_xor_sync(0xffffffffu, sum1, o);
            sq1  += __shfl_xor_sync(0xffffffffu, sq1,  o);
            sum2 += __shfl_xor_sync(0xffffffffu, sum2, o);
            sq2  += __shfl_xor_sync(0xffffffffu, sq2,  o);
        }
        float m1 = sum1 * (1.0f / 128.0f);
        float v1 = sq1 * (1.0f / 128.0f) - m1 * m1;
        float rs1 = rsqrtf(v1 + 1e-5f);
        float m2 = sum2 * (1.0f / 128.0f);
        float v2 = sq2 * (1.0f / 128.0f) - m2 * m2;
        float rs2 = rsqrtf(v2 + 1e-5f);

        const float* sg  = (const float*)(smem + SM_GAMMA);
        const float* sbt = (const float*)(smem + SM_BETA);
        #pragma unroll
        for (int n = 0; n < 16; n++) {
            int c = n * 8 + (lane & 3) * 2;
            if (r1 < N) {
                float2 o;
                o.x = fmaxf((acc[n][0] - m1) * rs1 * sg[c]     + sbt[c],     0.f);
                o.y = fmaxf((acc[n][1] - m1) * rs1 * sg[c + 1] + sbt[c + 1], 0.f);
                *reinterpret_cast<float2*>(out + (size_t)r1 * DD + c) = o;
            }
            if (r2 < N) {
                float2 o;
                o.x = fmaxf((acc[n][2] - m2) * rs2 * sg[c]     + sbt[c],     0.f);
                o.y = fmaxf((acc[n][3] - m2) * rs2 * sg[c + 1] + sbt[c + 1], 0.f);
                *reinterpret_cast<float2*>(out + (size_t)r2 * DD + c) = o;
            }
        }
        __syncwarp();
    }
}

// ---------------------------------------------------------------------------
extern "C" void kernel_launch(void* const* d_in, const int* in_sizes, int n_in,
                              void* d_out, int out_size) {
    const float* feature = (const float*)d_in[0];
    const float* snorm   = (const float*)d_in[1];
    const float* Wg      = (const float*)d_in[2];
    const float* gamma   = (const float*)d_in[3];
    const float* beta    = (const float*)d_in[4];
    const void*  src     = d_in[5];
    const void*  dst     = d_in[6];
    int N = in_sizes[1];
    int E = in_sizes[5];
    float* out = (float*)d_out;

    // 1) zero accumulator via async memset (graph-capturable memset node)
    void* hptr = nullptr;
    cudaGetSymbolAddress(&hptr, g_h4);
    cudaMemsetAsync(hptr, 0, (size_t)N * DD * sizeof(float), 0);

    // 2) gather + vector-atomic scatter: one warp per FOUR edges
    int nq = (E + 3) / 4;
    long long tt = (long long)nq * 32;
    k_scatter<<<(int)((tt + 255) / 256), 256>>>(feature, src, dst, E, N);

    // 3) bf16-split mma.sync GEMM + graphnorm + layernorm + relu
    cudaFuncSetAttribute(k_mma_norm,
                         cudaFuncAttributeMaxDynamicSharedMemorySize, SM_TOTAL);
    k_mma_norm<<<148, 256, SM_TOTAL>>>(snorm, Wg, gamma, beta, out, N);
}